// round 2
// baseline (speedup 1.0000x reference)
#include <cuda_runtime.h>
#include <math.h>

#define NPIX (512*512)
#define NB 16
#define SIG 0.125f
#define TAUC 0.125f
#define ALPHA_C 0.15f
#define MU_C 10.0f
#define EPS_C 1e-6f
#define INV1T (1.0f/1.125f)
#define FRLO 0.43000000000029104f
#define FRHI 0.5699999999953434f

// fused PD tiling
#define TT 64
#define KK 6
#define SS (TT + 2*KK)      // 76
#define PITCH 77
#define SMSZ (SS*PITCH)     // floats per smem array
#define NTH 768
#define PPT 8               // ceil(76*76/768)

// ---------------- device scratch (no runtime allocation allowed) ----------------
__device__ float g_tmpR[NB*NPIX];
__device__ float g_tmpM[NB*NPIX];
__device__ float g_x  [NB*NPIX];
__device__ float g_Nh [NB*NPIX];
__device__ float g_gm [NB*NPIX];
__device__ float g_Wx [NB*NPIX];
__device__ float g_Wy [NB*NPIX];
__device__ float g_u [2][NB*NPIX];
__device__ float g_ub[2][NB*NPIX];
__device__ float g_px[2][NB*NPIX];
__device__ float g_py[2][NB*NPIX];

__device__ unsigned g_hist1[NB*256];
__device__ unsigned g_histT[64*256];
__device__ unsigned g_tprefix[64];
__device__ unsigned g_trank[64];
__device__ float    g_selval[64];
__device__ float    g_lo[NB];
__device__ float    g_ihl[NB];
__device__ float    g_isig[NB];

__constant__ int c_ranksX[4] = {2621, 2622, 259521, 259522};
__constant__ int c_ranksG[2] = {131071, 131072};

// ---------------- horizontal 31-max-pool on R and max(G,B) ----------------
__global__ void k_hpool(const float* __restrict__ Iy) {
    int row = blockIdx.x, b = blockIdx.y;
    __shared__ float sR[512];
    __shared__ float sM[512];
    int j = threadIdx.x;
    const float* base = Iy + (size_t)b*3*NPIX + (size_t)row*512;
    float r = __ldg(base + j);
    float m = fmaxf(__ldg(base + NPIX + j), __ldg(base + 2*NPIX + j));
    sR[j] = r; sM[j] = m;
    __syncthreads();
    float mr = r, mm = m;
    #pragma unroll
    for (int t = -15; t <= 15; t++) {
        int jj = j + t; jj = jj < 0 ? 0 : (jj > 511 ? 511 : jj);
        mr = fmaxf(mr, sR[jj]);
        mm = fmaxf(mm, sM[jj]);
    }
    size_t o = (size_t)b*NPIX + (size_t)row*512 + j;
    g_tmpR[o] = mr; g_tmpM[o] = mm;
}

// ---------------- vertical 31-max-pool + x = |Rmax-GBmax| + R ----------------
__global__ void k_vpool_x(const float* __restrict__ Iy) {
    int b = blockIdx.z;
    int col0 = blockIdx.x * 32;
    int row0 = blockIdx.y * 64;
    __shared__ float sR[94][32];
    __shared__ float sM[94][32];
    int tid = threadIdx.y * 32 + threadIdx.x;
    for (int idx = tid; idx < 94*32; idx += 256) {
        int rr = idx >> 5, cc = idx & 31;
        int gr = row0 + rr - 15; gr = gr < 0 ? 0 : (gr > 511 ? 511 : gr);
        size_t o = (size_t)b*NPIX + (size_t)gr*512 + col0 + cc;
        sR[rr][cc] = g_tmpR[o];
        sM[rr][cc] = g_tmpM[o];
    }
    __syncthreads();
    int tx = threadIdx.x;
    for (int k = 0; k < 8; k++) {
        int r = threadIdx.y * 8 + k;
        float mr = -1e30f, mm = -1e30f;
        #pragma unroll
        for (int t = 0; t < 31; t++) {
            mr = fmaxf(mr, sR[r+t][tx]);
            mm = fmaxf(mm, sM[r+t][tx]);
        }
        int gr = row0 + r;
        size_t o = (size_t)b*NPIX + (size_t)gr*512 + col0 + tx;
        float R = __ldg(Iy + (size_t)b*3*NPIX + (size_t)gr*512 + col0 + tx);
        g_x[o] = fabsf(mr - mm) + R;
    }
}

// ---------------- radix-select (warp-aggregated atomics) ----------------
__global__ void k_zero_hists() {
    int i = blockIdx.x * blockDim.x + threadIdx.x;
    if (i < NB*256) g_hist1[i] = 0;
    for (int k = i; k < 64*256; k += gridDim.x * blockDim.x) g_histT[k] = 0;
}

__global__ void k_hist1(int which) {
    const float* src = which ? g_gm : g_x;
    int b = blockIdx.y;
    __shared__ unsigned h[256];
    for (int i = threadIdx.x; i < 256; i += blockDim.x) h[i] = 0;
    __syncthreads();
    const float* p = src + (size_t)b*NPIX;
    int lane = threadIdx.x & 31;
    for (int i = blockIdx.x * blockDim.x + threadIdx.x; i < NPIX; i += gridDim.x * blockDim.x) {
        unsigned v = __float_as_uint(__ldg(p + i));
        unsigned bin = v >> 24;
        unsigned m = __match_any_sync(0xffffffffu, bin);
        if (lane == __ffs(m) - 1) atomicAdd(&h[bin], (unsigned)__popc(m));
    }
    __syncthreads();
    for (int i = threadIdx.x; i < 256; i += blockDim.x)
        if (h[i]) atomicAdd(&g_hist1[b*256 + i], h[i]);
}

__global__ void k_histT(int which, int perB, int pass) {
    const float* src = which ? g_gm : g_x;
    int t = blockIdx.y;
    int b = t / perB;
    int shift = 8 * (4 - pass);
    unsigned mask = 0xFFFFFFFFu << (shift + 8);
    unsigned prefix = g_tprefix[t];
    __shared__ unsigned h[256];
    for (int i = threadIdx.x; i < 256; i += blockDim.x) h[i] = 0;
    __syncthreads();
    const float* p = src + (size_t)b*NPIX;
    int lane = threadIdx.x & 31;
    for (int i = blockIdx.x * blockDim.x + threadIdx.x; i < NPIX; i += gridDim.x * blockDim.x) {
        unsigned v = __float_as_uint(__ldg(p + i));
        bool ok = ((v & mask) == prefix);
        unsigned bin = ok ? ((v >> shift) & 0xFFu) : (0x100u + (unsigned)lane);
        unsigned m = __match_any_sync(0xffffffffu, bin);
        if (ok && lane == __ffs(m) - 1) atomicAdd(&h[bin], (unsigned)__popc(m));
    }
    __syncthreads();
    for (int i = threadIdx.x; i < 256; i += blockDim.x)
        if (h[i]) atomicAdd(&g_histT[t*256 + i], h[i]);
}

__global__ void k_resolve(int nT, int perB, int pass, int which) {
    int t = threadIdx.x;
    if (t < nT) {
        int b = t / perB;
        const unsigned* hist = (pass == 1) ? &g_hist1[b*256] : &g_histT[t*256];
        unsigned rank, prefix;
        if (pass == 1) {
            rank = (unsigned)(which ? c_ranksG[t % perB] : c_ranksX[t % perB]);
            prefix = 0u;
        } else {
            rank = g_trank[t]; prefix = g_tprefix[t];
        }
        unsigned cum = 0; int bkt = 255;
        for (int i = 0; i < 256; i++) {
            unsigned c = hist[i];
            if (cum + c > rank) { bkt = i; break; }
            cum += c;
        }
        rank -= cum;
        int shift = 8 * (4 - pass);
        prefix |= ((unsigned)bkt) << shift;
        if (pass == 4) g_selval[t] = __uint_as_float(prefix);
        else { g_tprefix[t] = prefix; g_trank[t] = rank; }
    }
    __syncthreads();
    for (int i = threadIdx.x; i < 64*256; i += blockDim.x) g_histT[i] = 0;
    if (pass == 4) for (int i = threadIdx.x; i < NB*256; i += blockDim.x) g_hist1[i] = 0;
}

__global__ void k_fin_x() {
    int b = threadIdx.x;
    if (b < NB) {
        float lo = g_selval[b*4+0]*(1.0f-FRLO) + g_selval[b*4+1]*FRLO;
        float hi = g_selval[b*4+2]*(1.0f-FRHI) + g_selval[b*4+3]*FRHI;
        g_lo[b] = lo;
        g_ihl[b] = 1.0f / (hi - lo + EPS_C);
    }
}

__global__ void k_fin_gm() {
    int b = threadIdx.x;
    if (b < NB) {
        float med = 0.5f * (g_selval[b*2+0] + g_selval[b*2+1]);
        float sig = fmaxf(med, EPS_C);
        g_isig[b] = 1.0f / sig;
    }
}

// ---------------- N_hat + grad magnitude ----------------
__global__ void k_nhat() {
    int b = blockIdx.z;
    int j = blockIdx.x * 32 + threadIdx.x;
    int i = blockIdx.y * 8 + threadIdx.y;
    size_t base = (size_t)b*NPIX;
    float lo = g_lo[b], inv = g_ihl[b];
    size_t o = base + (size_t)i*512 + j;
    float xc = __ldg(&g_x[o]);
    float n00 = fminf(fmaxf((xc - lo) * inv, 0.0f), 1.0f);
    float dx = 0.0f, dy = 0.0f;
    if (j < 511) {
        float xr = __ldg(&g_x[o + 1]);
        dx = fminf(fmaxf((xr - lo) * inv, 0.0f), 1.0f) - n00;
    }
    if (i < 511) {
        float xd = __ldg(&g_x[o + 512]);
        dy = fminf(fmaxf((xd - lo) * inv, 0.0f), 1.0f) - n00;
    }
    g_Nh[o] = n00;
    g_gm[o] = sqrtf(dx*dx + dy*dy + EPS_C);
}

// ---------------- Wx, Wy ----------------
__global__ void k_wxy() {
    int b = blockIdx.z;
    int j = blockIdx.x * 32 + threadIdx.x;
    int i = blockIdx.y * 8 + threadIdx.y;
    size_t base = (size_t)b*NPIX;
    float isig = g_isig[b];
    size_t o = base + (size_t)i*512 + j;
    float n00 = __ldg(&g_Nh[o]);
    float dx = (j < 511) ? (__ldg(&g_Nh[o + 1]) - n00) : 0.0f;
    float dy = (i < 511) ? (__ldg(&g_Nh[o + 512]) - n00) : 0.0f;
    g_Wx[o] = 1.0f + MU_C * expf(-fabsf(dx) * isig);
    g_Wy[o] = 1.0f + MU_C * expf(-fabsf(dy) * isig);
}

// ---------------- fused primal-dual: KK iterations per launch ----------------
// Per-thread registers hold u, px, py, alpha*Wx, alpha*Wy, Nh at 8 owned pixels.
// Shared memory holds only neighbor-visible fields: ub, px, py.
// Valid rectangle shrinks 1/side per iteration (pinned at true image edges);
// after KK iterations exactly the TTxTT interior is valid and written out.
template<bool FIRST, bool LAST>
__global__ void __launch_bounds__(NTH, 1) k_pdfuse(int rd, int wr, float* __restrict__ out) {
    extern __shared__ float sm[];
    float* s_ub = sm;
    float* s_px = sm + SMSZ;
    float* s_py = sm + 2*SMSZ;

    int b = blockIdx.z;
    int rx0 = blockIdx.x * TT - KK;
    int ry0 = blockIdx.y * TT - KK;
    size_t base = (size_t)b * NPIX;
    int tid = threadIdx.x;

    float ru[PPT], rpx[PPT], rpy[PPT], rbx[PPT], rby[PPT], rnh[PPT];

    // ---- load ----
    #pragma unroll
    for (int k = 0; k < PPT; k++) {
        int p = tid + k*NTH;
        if (p < SS*SS) {
            int r = p / SS, c = p % SS;
            int gi = ry0 + r, gj = rx0 + c;
            if (gi >= 0 && gi < 512 && gj >= 0 && gj < 512) {
                size_t go = base + (size_t)gi*512 + gj;
                int o = r*PITCH + c;
                float nh = __ldg(&g_Nh[go]);
                rnh[k] = nh;
                rbx[k] = ALPHA_C * __ldg(&g_Wx[go]);
                rby[k] = ALPHA_C * __ldg(&g_Wy[go]);
                if (FIRST) {
                    ru[k] = nh; s_ub[o] = nh;
                    rpx[k] = 0.0f; rpy[k] = 0.0f;
                } else {
                    ru[k]  = __ldg(&g_u [rd][go]);
                    s_ub[o] = __ldg(&g_ub[rd][go]);
                    rpx[k] = __ldg(&g_px[rd][go]);
                    rpy[k] = __ldg(&g_py[rd][go]);
                }
            }
        }
    }
    __syncthreads();

    // valid rectangle (local coords); pinned at true image edges
    int rA = (ry0 < 0) ? -ry0 : 0;
    int rB = (511 - ry0 < SS-1) ? (511 - ry0) : (SS-1);
    int cA = (rx0 < 0) ? -rx0 : 0;
    int cB = (511 - rx0 < SS-1) ? (511 - rx0) : (SS-1);

    for (int t = 0; t < KK; t++) {
        // ---- dual phase over [rA,rB]x[cA,cB] ----
        #pragma unroll
        for (int k = 0; k < PPT; k++) {
            int p = tid + k*NTH;
            if (p < SS*SS) {
                int r = p / SS, c = p % SS;
                if (r >= rA && r <= rB && c >= cA && c <= cB) {
                    int gi = ry0 + r, gj = rx0 + c;
                    int o = r*PITCH + c;
                    float ubc = s_ub[o];
                    float dx = (gj < 511) ? (s_ub[o + 1]     - ubc) : 0.0f;
                    float dy = (gi < 511) ? (s_ub[o + PITCH] - ubc) : 0.0f;
                    float pxn = fminf(fmaxf(rpx[k] + SIG*dx, -rbx[k]), rbx[k]);
                    float pyn = fminf(fmaxf(rpy[k] + SIG*dy, -rby[k]), rby[k]);
                    rpx[k] = pxn; rpy[k] = pyn;
                    s_px[o] = pxn; s_py[o] = pyn;
                }
            }
        }
        __syncthreads();

        int rA2 = rA + ((ry0 + rA) != 0);
        int rB2 = rB - ((ry0 + rB) != 511);
        int cA2 = cA + ((rx0 + cA) != 0);
        int cB2 = cB - ((rx0 + cB) != 511);

        // ---- primal phase over shrunk rect ----
        #pragma unroll
        for (int k = 0; k < PPT; k++) {
            int p = tid + k*NTH;
            if (p < SS*SS) {
                int r = p / SS, c = p % SS;
                if (r >= rA2 && r <= rB2 && c >= cA2 && c <= cB2) {
                    int gi = ry0 + r, gj = rx0 + c;
                    int o = r*PITCH + c;
                    float pxl = (gj > 0) ? s_px[o - 1]     : 0.0f;
                    float pyu = (gi > 0) ? s_py[o - PITCH] : 0.0f;
                    float uc = ru[k];
                    float un = (uc + TAUC*(rpx[k] - pxl + rpy[k] - pyu) + TAUC*rnh[k]) * INV1T;
                    s_ub[o] = 2.0f*un - uc;
                    ru[k] = un;
                }
            }
        }
        __syncthreads();
        rA = rA2; rB = rB2; cA = cA2; cB = cB2;
    }

    // ---- store interior [KK, KK+TT) ----
    #pragma unroll
    for (int k = 0; k < PPT; k++) {
        int p = tid + k*NTH;
        if (p < SS*SS) {
            int r = p / SS, c = p % SS;
            if (r >= KK && r < KK+TT && c >= KK && c < KK+TT) {
                int gi = ry0 + r, gj = rx0 + c;
                size_t go = base + (size_t)gi*512 + gj;
                int o = r*PITCH + c;
                if (LAST) {
                    out[go] = fminf(fmaxf(ru[k], 0.0f), 1.0f);
                } else {
                    g_u [wr][go] = ru[k];
                    g_ub[wr][go] = s_ub[o];
                    g_px[wr][go] = rpx[k];
                    g_py[wr][go] = rpy[k];
                }
            }
        }
    }
}

// ---------------- launch ----------------
extern "C" void kernel_launch(void* const* d_in, const int* in_sizes, int n_in,
                              void* d_out, int out_size) {
    const float* Iy = (const float*)d_in[0];
    float* out = (float*)d_out;

    static bool attr_done = false;
    const int smbytes = 3 * SMSZ * sizeof(float);
    if (!attr_done) {
        cudaFuncSetAttribute(k_pdfuse<true,false>,  cudaFuncAttributeMaxDynamicSharedMemorySize, smbytes);
        cudaFuncSetAttribute(k_pdfuse<false,false>, cudaFuncAttributeMaxDynamicSharedMemorySize, smbytes);
        cudaFuncSetAttribute(k_pdfuse<false,true>,  cudaFuncAttributeMaxDynamicSharedMemorySize, smbytes);
        attr_done = true;
    }

    dim3 b32x8(32, 8);
    dim3 gFull(16, 64, NB);

    k_hpool  <<<dim3(512, NB), 512>>>(Iy);
    k_vpool_x<<<dim3(16, 8, NB), b32x8>>>(Iy);

    k_zero_hists<<<16, 256>>>();

    // quantiles of x (p01, p99): ranks k and k+1 for linear interpolation
    k_hist1<<<dim3(16, NB), 256>>>(0);
    k_resolve<<<1, 256>>>(64, 4, 1, 0);
    for (int pass = 2; pass <= 4; pass++) {
        k_histT<<<dim3(8, 64), 256>>>(0, 4, pass);
        k_resolve<<<1, 256>>>(64, 4, pass, 0);
    }
    k_fin_x<<<1, 32>>>();

    k_nhat<<<gFull, b32x8>>>();

    // median of grad magnitude
    k_hist1<<<dim3(16, NB), 256>>>(1);
    k_resolve<<<1, 256>>>(32, 2, 1, 1);
    for (int pass = 2; pass <= 4; pass++) {
        k_histT<<<dim3(8, 32), 256>>>(1, 2, pass);
        k_resolve<<<1, 256>>>(32, 2, pass, 1);
    }
    k_fin_gm<<<1, 32>>>();

    k_wxy<<<gFull, b32x8>>>();

    // 30 PD iterations = 5 fused launches of 6
    dim3 gTile(8, 8, NB);
    k_pdfuse<true,  false><<<gTile, NTH, smbytes>>>(0, 0, nullptr);
    k_pdfuse<false, false><<<gTile, NTH, smbytes>>>(0, 1, nullptr);
    k_pdfuse<false, false><<<gTile, NTH, smbytes>>>(1, 0, nullptr);
    k_pdfuse<false, false><<<gTile, NTH, smbytes>>>(0, 1, nullptr);
    k_pdfuse<false, true ><<<gTile, NTH, smbytes>>>(1, 0, out);
}

// round 3
// speedup vs baseline: 1.7850x; 1.7850x over previous
#include <cuda_runtime.h>
#include <math.h>

#define NPIX (512*512)
#define NB 16
#define SIG 0.125f
#define TAUC 0.125f
#define ALPHA_C 0.15f
#define MU_C 10.0f
#define EPS_C 1e-6f
#define INV1T (1.0f/1.125f)
#define FRLO 0.43000000000029104f
#define FRHI 0.5699999999953434f

// fused PD tiling
#define TT 64
#define KK 6
#define SS (TT + 2*KK)      // 76
#define PITCH 77
#define SMSZ (SS*PITCH)     // floats per smem array
#define NTH 608             // 76 x 8
#define PPT 10              // ceil(76/8) rows per thread

// ---------------- device scratch (no runtime allocation allowed) ----------------
__device__ float g_tmpR[NB*NPIX];
__device__ float g_tmpM[NB*NPIX];
__device__ float g_x  [NB*NPIX];
__device__ float g_Nh [NB*NPIX];
__device__ float g_gm [NB*NPIX];
__device__ float g_Wx [NB*NPIX];
__device__ float g_Wy [NB*NPIX];
__device__ float g_u [2][NB*NPIX];
__device__ float g_ub[2][NB*NPIX];
__device__ float g_px[2][NB*NPIX];
__device__ float g_py[2][NB*NPIX];

__device__ unsigned g_hist1[NB*256];
__device__ unsigned g_histT[64*256];
__device__ unsigned g_tprefix[64];
__device__ unsigned g_trank[64];
__device__ float    g_selval[64];
__device__ float    g_lo[NB];
__device__ float    g_ihl[NB];
__device__ float    g_isig[NB];

__constant__ int c_ranksX[4] = {2621, 2622, 259521, 259522};
__constant__ int c_ranksG[2] = {131071, 131072};

// ---------------- horizontal 31-max-pool on R and max(G,B) ----------------
__global__ void k_hpool(const float* __restrict__ Iy) {
    int row = blockIdx.x, b = blockIdx.y;
    __shared__ float sR[512];
    __shared__ float sM[512];
    int j = threadIdx.x;
    const float* base = Iy + (size_t)b*3*NPIX + (size_t)row*512;
    float r = __ldg(base + j);
    float m = fmaxf(__ldg(base + NPIX + j), __ldg(base + 2*NPIX + j));
    sR[j] = r; sM[j] = m;
    __syncthreads();
    float mr = r, mm = m;
    #pragma unroll
    for (int t = -15; t <= 15; t++) {
        int jj = j + t; jj = jj < 0 ? 0 : (jj > 511 ? 511 : jj);
        mr = fmaxf(mr, sR[jj]);
        mm = fmaxf(mm, sM[jj]);
    }
    size_t o = (size_t)b*NPIX + (size_t)row*512 + j;
    g_tmpR[o] = mr; g_tmpM[o] = mm;
}

// ---------------- vertical 31-max-pool + x = |Rmax-GBmax| + R ----------------
__global__ void k_vpool_x(const float* __restrict__ Iy) {
    int b = blockIdx.z;
    int col0 = blockIdx.x * 32;
    int row0 = blockIdx.y * 64;
    __shared__ float sR[94][32];
    __shared__ float sM[94][32];
    int tid = threadIdx.y * 32 + threadIdx.x;
    for (int idx = tid; idx < 94*32; idx += 256) {
        int rr = idx >> 5, cc = idx & 31;
        int gr = row0 + rr - 15; gr = gr < 0 ? 0 : (gr > 511 ? 511 : gr);
        size_t o = (size_t)b*NPIX + (size_t)gr*512 + col0 + cc;
        sR[rr][cc] = g_tmpR[o];
        sM[rr][cc] = g_tmpM[o];
    }
    __syncthreads();
    int tx = threadIdx.x;
    for (int k = 0; k < 8; k++) {
        int r = threadIdx.y * 8 + k;
        float mr = -1e30f, mm = -1e30f;
        #pragma unroll
        for (int t = 0; t < 31; t++) {
            mr = fmaxf(mr, sR[r+t][tx]);
            mm = fmaxf(mm, sM[r+t][tx]);
        }
        int gr = row0 + r;
        size_t o = (size_t)b*NPIX + (size_t)gr*512 + col0 + tx;
        float R = __ldg(Iy + (size_t)b*3*NPIX + (size_t)gr*512 + col0 + tx);
        g_x[o] = fabsf(mr - mm) + R;
    }
}

// ---------------- radix-select (8-way replicated smem histograms, float4) ----------------
__global__ void k_zero_hists() {
    int i = blockIdx.x * blockDim.x + threadIdx.x;
    if (i < NB*256) g_hist1[i] = 0;
    for (int k = i; k < 64*256; k += gridDim.x * blockDim.x) g_histT[k] = 0;
}

__global__ void k_hist1(int which) {
    const float* src = which ? g_gm : g_x;
    int b = blockIdx.y;
    __shared__ unsigned h[8*256];
    for (int i = threadIdx.x; i < 8*256; i += blockDim.x) h[i] = 0;
    __syncthreads();
    unsigned rep = (threadIdx.x & 7) * 256;
    const float4* p = (const float4*)(src + (size_t)b*NPIX);
    for (int i = blockIdx.x * blockDim.x + threadIdx.x; i < NPIX/4; i += gridDim.x * blockDim.x) {
        float4 v = __ldg(p + i);
        atomicAdd(&h[rep + (__float_as_uint(v.x) >> 24)], 1u);
        atomicAdd(&h[rep + (__float_as_uint(v.y) >> 24)], 1u);
        atomicAdd(&h[rep + (__float_as_uint(v.z) >> 24)], 1u);
        atomicAdd(&h[rep + (__float_as_uint(v.w) >> 24)], 1u);
    }
    __syncthreads();
    for (int i = threadIdx.x; i < 256; i += blockDim.x) {
        unsigned s = 0;
        #pragma unroll
        for (int r = 0; r < 8; r++) s += h[r*256 + i];
        if (s) atomicAdd(&g_hist1[b*256 + i], s);
    }
}

__global__ void k_histT(int which, int perB, int pass) {
    const float* src = which ? g_gm : g_x;
    int t = blockIdx.y;
    int b = t / perB;
    int shift = 8 * (4 - pass);
    unsigned mask = 0xFFFFFFFFu << (shift + 8);
    unsigned prefix = g_tprefix[t];
    __shared__ unsigned h[8*256];
    for (int i = threadIdx.x; i < 8*256; i += blockDim.x) h[i] = 0;
    __syncthreads();
    unsigned rep = (threadIdx.x & 7) * 256;
    const float4* p = (const float4*)(src + (size_t)b*NPIX);
    for (int i = blockIdx.x * blockDim.x + threadIdx.x; i < NPIX/4; i += gridDim.x * blockDim.x) {
        float4 vv = __ldg(p + i);
        unsigned v;
        v = __float_as_uint(vv.x); if ((v & mask) == prefix) atomicAdd(&h[rep + ((v >> shift) & 0xFF)], 1u);
        v = __float_as_uint(vv.y); if ((v & mask) == prefix) atomicAdd(&h[rep + ((v >> shift) & 0xFF)], 1u);
        v = __float_as_uint(vv.z); if ((v & mask) == prefix) atomicAdd(&h[rep + ((v >> shift) & 0xFF)], 1u);
        v = __float_as_uint(vv.w); if ((v & mask) == prefix) atomicAdd(&h[rep + ((v >> shift) & 0xFF)], 1u);
    }
    __syncthreads();
    for (int i = threadIdx.x; i < 256; i += blockDim.x) {
        unsigned s = 0;
        #pragma unroll
        for (int r = 0; r < 8; r++) s += h[r*256 + i];
        if (s) atomicAdd(&g_histT[t*256 + i], s);
    }
}

__global__ void k_resolve(int nT, int perB, int pass, int which) {
    int t = threadIdx.x;
    if (t < nT) {
        int b = t / perB;
        const unsigned* hist = (pass == 1) ? &g_hist1[b*256] : &g_histT[t*256];
        unsigned rank, prefix;
        if (pass == 1) {
            rank = (unsigned)(which ? c_ranksG[t % perB] : c_ranksX[t % perB]);
            prefix = 0u;
        } else {
            rank = g_trank[t]; prefix = g_tprefix[t];
        }
        unsigned cum = 0; int bkt = 255;
        for (int i = 0; i < 256; i++) {
            unsigned c = hist[i];
            if (cum + c > rank) { bkt = i; break; }
            cum += c;
        }
        rank -= cum;
        int shift = 8 * (4 - pass);
        prefix |= ((unsigned)bkt) << shift;
        if (pass == 4) g_selval[t] = __uint_as_float(prefix);
        else { g_tprefix[t] = prefix; g_trank[t] = rank; }
    }
    __syncthreads();
    for (int i = threadIdx.x; i < 64*256; i += blockDim.x) g_histT[i] = 0;
    if (pass == 4) for (int i = threadIdx.x; i < NB*256; i += blockDim.x) g_hist1[i] = 0;
}

__global__ void k_fin_x() {
    int b = threadIdx.x;
    if (b < NB) {
        float lo = g_selval[b*4+0]*(1.0f-FRLO) + g_selval[b*4+1]*FRLO;
        float hi = g_selval[b*4+2]*(1.0f-FRHI) + g_selval[b*4+3]*FRHI;
        g_lo[b] = lo;
        g_ihl[b] = 1.0f / (hi - lo + EPS_C);
    }
}

__global__ void k_fin_gm() {
    int b = threadIdx.x;
    if (b < NB) {
        float med = 0.5f * (g_selval[b*2+0] + g_selval[b*2+1]);
        float sig = fmaxf(med, EPS_C);
        g_isig[b] = 1.0f / sig;
    }
}

// ---------------- N_hat + grad magnitude ----------------
__global__ void k_nhat() {
    int b = blockIdx.z;
    int j = blockIdx.x * 32 + threadIdx.x;
    int i = blockIdx.y * 8 + threadIdx.y;
    size_t base = (size_t)b*NPIX;
    float lo = g_lo[b], inv = g_ihl[b];
    size_t o = base + (size_t)i*512 + j;
    float xc = __ldg(&g_x[o]);
    float n00 = fminf(fmaxf((xc - lo) * inv, 0.0f), 1.0f);
    float dx = 0.0f, dy = 0.0f;
    if (j < 511) {
        float xr = __ldg(&g_x[o + 1]);
        dx = fminf(fmaxf((xr - lo) * inv, 0.0f), 1.0f) - n00;
    }
    if (i < 511) {
        float xd = __ldg(&g_x[o + 512]);
        dy = fminf(fmaxf((xd - lo) * inv, 0.0f), 1.0f) - n00;
    }
    g_Nh[o] = n00;
    g_gm[o] = sqrtf(dx*dx + dy*dy + EPS_C);
}

// ---------------- Wx, Wy ----------------
__global__ void k_wxy() {
    int b = blockIdx.z;
    int j = blockIdx.x * 32 + threadIdx.x;
    int i = blockIdx.y * 8 + threadIdx.y;
    size_t base = (size_t)b*NPIX;
    float isig = g_isig[b];
    size_t o = base + (size_t)i*512 + j;
    float n00 = __ldg(&g_Nh[o]);
    float dx = (j < 511) ? (__ldg(&g_Nh[o + 1]) - n00) : 0.0f;
    float dy = (i < 511) ? (__ldg(&g_Nh[o + 512]) - n00) : 0.0f;
    g_Wx[o] = 1.0f + MU_C * expf(-fabsf(dx) * isig);
    g_Wy[o] = 1.0f + MU_C * expf(-fabsf(dy) * isig);
}

// ---------------- fused primal-dual: KK iterations per launch ----------------
// Registers hold only u, Nh, alpha*Wx, alpha*Wy (no px/py duplication).
// px/py/ub live in smem; dual does owner-only RMW on s_px/s_py (no hazard).
// Thread layout (76, 8): column fixed per thread, no div/mod in phases.
template<bool FIRST, bool LAST>
__global__ void __launch_bounds__(NTH, 1) k_pdfuse(int rd, int wr, float* __restrict__ out) {
    extern __shared__ float sm[];
    float* s_ub = sm;
    float* s_px = sm + SMSZ;
    float* s_py = sm + 2*SMSZ;

    int b = blockIdx.z;
    int rx0 = blockIdx.x * TT - KK;
    int ry0 = blockIdx.y * TT - KK;
    size_t base = (size_t)b * NPIX;
    int tx = threadIdx.x;            // local column 0..75
    int ty = threadIdx.y;            // row group 0..7
    int gj = rx0 + tx;
    bool jok = (gj >= 0) && (gj < 512);

    float ru[PPT], rnh[PPT], rbx[PPT], rby[PPT];

    // ---- load ----
    #pragma unroll
    for (int k = 0; k < PPT; k++) {
        int r = ty + 8*k;
        if (r < SS) {
            int gi = ry0 + r;
            int o = r*PITCH + tx;
            if (jok && gi >= 0 && gi < 512) {
                size_t go = base + (size_t)gi*512 + gj;
                float nh = __ldg(&g_Nh[go]);
                rnh[k] = nh;
                rbx[k] = ALPHA_C * __ldg(&g_Wx[go]);
                rby[k] = ALPHA_C * __ldg(&g_Wy[go]);
                if (FIRST) {
                    ru[k] = nh; s_ub[o] = nh;
                    s_px[o] = 0.0f; s_py[o] = 0.0f;
                } else {
                    ru[k]  = __ldg(&g_u [rd][go]);
                    s_ub[o] = __ldg(&g_ub[rd][go]);
                    s_px[o] = __ldg(&g_px[rd][go]);
                    s_py[o] = __ldg(&g_py[rd][go]);
                }
            }
        }
    }
    __syncthreads();

    // valid rectangle (local coords); pinned at true image edges
    int rA = (ry0 < 0) ? -ry0 : 0;
    int rB = (511 - ry0 < SS-1) ? (511 - ry0) : (SS-1);
    int cA = (rx0 < 0) ? -rx0 : 0;
    int cB = (511 - rx0 < SS-1) ? (511 - rx0) : (SS-1);

    for (int t = 0; t < KK; t++) {
        // ---- dual phase over [rA,rB]x[cA,cB] ----
        bool cok = (tx >= cA) && (tx <= cB);
        #pragma unroll
        for (int k = 0; k < PPT; k++) {
            int r = ty + 8*k;
            if (r < SS && cok && r >= rA && r <= rB) {
                int gi = ry0 + r;
                int o = r*PITCH + tx;
                float ubc = s_ub[o];
                float dx = (gj < 511) ? (s_ub[o + 1]     - ubc) : 0.0f;
                float dy = (gi < 511) ? (s_ub[o + PITCH] - ubc) : 0.0f;
                float pxn = fminf(fmaxf(s_px[o] + SIG*dx, -rbx[k]), rbx[k]);
                float pyn = fminf(fmaxf(s_py[o] + SIG*dy, -rby[k]), rby[k]);
                s_px[o] = pxn; s_py[o] = pyn;
            }
        }
        __syncthreads();

        int rA2 = rA + ((ry0 + rA) != 0);
        int rB2 = rB - ((ry0 + rB) != 511);
        int cA2 = cA + ((rx0 + cA) != 0);
        int cB2 = cB - ((rx0 + cB) != 511);

        // ---- primal phase over shrunk rect ----
        bool cok2 = (tx >= cA2) && (tx <= cB2);
        #pragma unroll
        for (int k = 0; k < PPT; k++) {
            int r = ty + 8*k;
            if (r < SS && cok2 && r >= rA2 && r <= rB2) {
                int gi = ry0 + r;
                int o = r*PITCH + tx;
                float pxl = (gj > 0) ? s_px[o - 1]     : 0.0f;
                float pyu = (gi > 0) ? s_py[o - PITCH] : 0.0f;
                float uc = ru[k];
                float un = (uc + TAUC*(s_px[o] - pxl + s_py[o] - pyu) + TAUC*rnh[k]) * INV1T;
                s_ub[o] = 2.0f*un - uc;
                ru[k] = un;
            }
        }
        __syncthreads();
        rA = rA2; rB = rB2; cA = cA2; cB = cB2;
    }

    // ---- store interior [KK, KK+TT) ----
    if (tx >= KK && tx < KK+TT) {
        #pragma unroll
        for (int k = 0; k < PPT; k++) {
            int r = ty + 8*k;
            if (r >= KK && r < KK+TT) {
                int gi = ry0 + r;
                size_t go = base + (size_t)gi*512 + gj;
                int o = r*PITCH + tx;
                if (LAST) {
                    out[go] = fminf(fmaxf(ru[k], 0.0f), 1.0f);
                } else {
                    g_u [wr][go] = ru[k];
                    g_ub[wr][go] = s_ub[o];
                    g_px[wr][go] = s_px[o];
                    g_py[wr][go] = s_py[o];
                }
            }
        }
    }
}

// ---------------- launch ----------------
extern "C" void kernel_launch(void* const* d_in, const int* in_sizes, int n_in,
                              void* d_out, int out_size) {
    const float* Iy = (const float*)d_in[0];
    float* out = (float*)d_out;

    const int smbytes = 3 * SMSZ * sizeof(float);
    cudaFuncSetAttribute(k_pdfuse<true,false>,  cudaFuncAttributeMaxDynamicSharedMemorySize, smbytes);
    cudaFuncSetAttribute(k_pdfuse<false,false>, cudaFuncAttributeMaxDynamicSharedMemorySize, smbytes);
    cudaFuncSetAttribute(k_pdfuse<false,true>,  cudaFuncAttributeMaxDynamicSharedMemorySize, smbytes);

    dim3 b32x8(32, 8);
    dim3 gFull(16, 64, NB);

    k_hpool  <<<dim3(512, NB), 512>>>(Iy);
    k_vpool_x<<<dim3(16, 8, NB), b32x8>>>(Iy);

    k_zero_hists<<<16, 256>>>();

    // quantiles of x (p01, p99): ranks k and k+1 for linear interpolation
    k_hist1<<<dim3(64, NB), 256>>>(0);
    k_resolve<<<1, 256>>>(64, 4, 1, 0);
    for (int pass = 2; pass <= 4; pass++) {
        k_histT<<<dim3(32, 64), 256>>>(0, 4, pass);
        k_resolve<<<1, 256>>>(64, 4, pass, 0);
    }
    k_fin_x<<<1, 32>>>();

    k_nhat<<<gFull, b32x8>>>();

    // median of grad magnitude
    k_hist1<<<dim3(64, NB), 256>>>(1);
    k_resolve<<<1, 256>>>(32, 2, 1, 1);
    for (int pass = 2; pass <= 4; pass++) {
        k_histT<<<dim3(32, 32), 256>>>(1, 2, pass);
        k_resolve<<<1, 256>>>(32, 2, pass, 1);
    }
    k_fin_gm<<<1, 32>>>();

    k_wxy<<<gFull, b32x8>>>();

    // 30 PD iterations = 5 fused launches of 6
    dim3 bTile(SS, 8);
    dim3 gTile(8, 8, NB);
    k_pdfuse<true,  false><<<gTile, bTile, smbytes>>>(0, 0, nullptr);
    k_pdfuse<false, false><<<gTile, bTile, smbytes>>>(0, 1, nullptr);
    k_pdfuse<false, false><<<gTile, bTile, smbytes>>>(1, 0, nullptr);
    k_pdfuse<false, false><<<gTile, bTile, smbytes>>>(0, 1, nullptr);
    k_pdfuse<false, true ><<<gTile, bTile, smbytes>>>(1, 0, out);
}

// round 4
// speedup vs baseline: 2.0288x; 1.1365x over previous
#include <cuda_runtime.h>
#include <math.h>

#define NPIX (512*512)
#define NB 16
#define SIG 0.125f
#define TAUC 0.125f
#define ALPHA_C 0.15f
#define MU_C 10.0f
#define EPS_C 1e-6f
#define INV1T (1.0f/1.125f)
#define FRLO 0.43000000000029104f
#define FRHI 0.5699999999953434f

// fused PD tiling
#define TT 48
#define KK 6
#define SS (TT + 2*KK)      // 60
#define PITCH 61
#define SMSZ (SS*PITCH)     // floats per smem array
#define NTH 480             // 60 x 8
#define PPT 8               // ceil(60/8) rows per thread
#define NTILE 11            // ceil(512/48)

// ---------------- device scratch (no runtime allocation allowed) ----------------
__device__ float g_tmpR[NB*NPIX];
__device__ float g_tmpM[NB*NPIX];
__device__ float g_x  [NB*NPIX];
__device__ float g_Nh [NB*NPIX];
__device__ float g_gm [NB*NPIX];
__device__ float g_Wx [NB*NPIX];   // holds ALPHA*Wx (pre-multiplied)
__device__ float g_Wy [NB*NPIX];   // holds ALPHA*Wy
__device__ float g_u [2][NB*NPIX];
__device__ float g_ub[2][NB*NPIX];
__device__ float g_px[2][NB*NPIX];
__device__ float g_py[2][NB*NPIX];

__device__ unsigned g_hist1[NB*256];
__device__ unsigned g_histT[64*256];
__device__ unsigned g_tprefix[64];
__device__ unsigned g_trank[64];
__device__ float    g_selval[64];
__device__ float    g_lo[NB];
__device__ float    g_ihl[NB];
__device__ float    g_isig[NB];

__constant__ int c_ranksX[4] = {2621, 2622, 259521, 259522};
__constant__ int c_ranksG[2] = {131071, 131072};

// ---------------- horizontal 31-max-pool on R and max(G,B) ----------------
__global__ void k_hpool(const float* __restrict__ Iy) {
    int row = blockIdx.x, b = blockIdx.y;
    __shared__ float sR[512];
    __shared__ float sM[512];
    int j = threadIdx.x;
    const float* base = Iy + (size_t)b*3*NPIX + (size_t)row*512;
    float r = __ldg(base + j);
    float m = fmaxf(__ldg(base + NPIX + j), __ldg(base + 2*NPIX + j));
    sR[j] = r; sM[j] = m;
    __syncthreads();
    float mr = r, mm = m;
    #pragma unroll
    for (int t = -15; t <= 15; t++) {
        int jj = j + t; jj = jj < 0 ? 0 : (jj > 511 ? 511 : jj);
        mr = fmaxf(mr, sR[jj]);
        mm = fmaxf(mm, sM[jj]);
    }
    size_t o = (size_t)b*NPIX + (size_t)row*512 + j;
    g_tmpR[o] = mr; g_tmpM[o] = mm;
}

// ---------------- vertical 31-max-pool + x = |Rmax-GBmax| + R ----------------
__global__ void k_vpool_x(const float* __restrict__ Iy) {
    int b = blockIdx.z;
    int col0 = blockIdx.x * 32;
    int row0 = blockIdx.y * 64;
    __shared__ float sR[94][32];
    __shared__ float sM[94][32];
    int tid = threadIdx.y * 32 + threadIdx.x;
    for (int idx = tid; idx < 94*32; idx += 256) {
        int rr = idx >> 5, cc = idx & 31;
        int gr = row0 + rr - 15; gr = gr < 0 ? 0 : (gr > 511 ? 511 : gr);
        size_t o = (size_t)b*NPIX + (size_t)gr*512 + col0 + cc;
        sR[rr][cc] = g_tmpR[o];
        sM[rr][cc] = g_tmpM[o];
    }
    __syncthreads();
    int tx = threadIdx.x;
    for (int k = 0; k < 8; k++) {
        int r = threadIdx.y * 8 + k;
        float mr = -1e30f, mm = -1e30f;
        #pragma unroll
        for (int t = 0; t < 31; t++) {
            mr = fmaxf(mr, sR[r+t][tx]);
            mm = fmaxf(mm, sM[r+t][tx]);
        }
        int gr = row0 + r;
        size_t o = (size_t)b*NPIX + (size_t)gr*512 + col0 + tx;
        float R = __ldg(Iy + (size_t)b*3*NPIX + (size_t)gr*512 + col0 + tx);
        g_x[o] = fabsf(mr - mm) + R;
    }
}

// ---------------- radix-select (8-way replicated smem histograms, float4) ----------------
__global__ void k_zero_hists() {
    int i = blockIdx.x * blockDim.x + threadIdx.x;
    if (i < NB*256) g_hist1[i] = 0;
    for (int k = i; k < 64*256; k += gridDim.x * blockDim.x) g_histT[k] = 0;
}

__global__ void k_hist1(int which) {
    const float* src = which ? g_gm : g_x;
    int b = blockIdx.y;
    __shared__ unsigned h[8*256];
    for (int i = threadIdx.x; i < 8*256; i += blockDim.x) h[i] = 0;
    __syncthreads();
    unsigned rep = (threadIdx.x & 7) * 256;
    const float4* p = (const float4*)(src + (size_t)b*NPIX);
    for (int i = blockIdx.x * blockDim.x + threadIdx.x; i < NPIX/4; i += gridDim.x * blockDim.x) {
        float4 v = __ldg(p + i);
        atomicAdd(&h[rep + (__float_as_uint(v.x) >> 24)], 1u);
        atomicAdd(&h[rep + (__float_as_uint(v.y) >> 24)], 1u);
        atomicAdd(&h[rep + (__float_as_uint(v.z) >> 24)], 1u);
        atomicAdd(&h[rep + (__float_as_uint(v.w) >> 24)], 1u);
    }
    __syncthreads();
    for (int i = threadIdx.x; i < 256; i += blockDim.x) {
        unsigned s = 0;
        #pragma unroll
        for (int r = 0; r < 8; r++) s += h[r*256 + i];
        if (s) atomicAdd(&g_hist1[b*256 + i], s);
    }
}

__global__ void k_histT(int which, int perB, int pass) {
    const float* src = which ? g_gm : g_x;
    int t = blockIdx.y;
    int b = t / perB;
    int shift = 8 * (4 - pass);
    unsigned mask = 0xFFFFFFFFu << (shift + 8);
    unsigned prefix = g_tprefix[t];
    __shared__ unsigned h[8*256];
    for (int i = threadIdx.x; i < 8*256; i += blockDim.x) h[i] = 0;
    __syncthreads();
    unsigned rep = (threadIdx.x & 7) * 256;
    const float4* p = (const float4*)(src + (size_t)b*NPIX);
    for (int i = blockIdx.x * blockDim.x + threadIdx.x; i < NPIX/4; i += gridDim.x * blockDim.x) {
        float4 vv = __ldg(p + i);
        unsigned v;
        v = __float_as_uint(vv.x); if ((v & mask) == prefix) atomicAdd(&h[rep + ((v >> shift) & 0xFF)], 1u);
        v = __float_as_uint(vv.y); if ((v & mask) == prefix) atomicAdd(&h[rep + ((v >> shift) & 0xFF)], 1u);
        v = __float_as_uint(vv.z); if ((v & mask) == prefix) atomicAdd(&h[rep + ((v >> shift) & 0xFF)], 1u);
        v = __float_as_uint(vv.w); if ((v & mask) == prefix) atomicAdd(&h[rep + ((v >> shift) & 0xFF)], 1u);
    }
    __syncthreads();
    for (int i = threadIdx.x; i < 256; i += blockDim.x) {
        unsigned s = 0;
        #pragma unroll
        for (int r = 0; r < 8; r++) s += h[r*256 + i];
        if (s) atomicAdd(&g_histT[t*256 + i], s);
    }
}

// resolve + (on pass 4) finalize lo/ihl or isig
__global__ void k_resolve(int nT, int perB, int pass, int which) {
    int t = threadIdx.x;
    if (t < nT) {
        int b = t / perB;
        const unsigned* hist = (pass == 1) ? &g_hist1[b*256] : &g_histT[t*256];
        unsigned rank, prefix;
        if (pass == 1) {
            rank = (unsigned)(which ? c_ranksG[t % perB] : c_ranksX[t % perB]);
            prefix = 0u;
        } else {
            rank = g_trank[t]; prefix = g_tprefix[t];
        }
        unsigned cum = 0; int bkt = 255;
        for (int i = 0; i < 256; i++) {
            unsigned c = hist[i];
            if (cum + c > rank) { bkt = i; break; }
            cum += c;
        }
        rank -= cum;
        int shift = 8 * (4 - pass);
        prefix |= ((unsigned)bkt) << shift;
        if (pass == 4) g_selval[t] = __uint_as_float(prefix);
        else { g_tprefix[t] = prefix; g_trank[t] = rank; }
    }
    __syncthreads();
    for (int i = threadIdx.x; i < 64*256; i += blockDim.x) g_histT[i] = 0;
    if (pass == 4) {
        for (int i = threadIdx.x; i < NB*256; i += blockDim.x) g_hist1[i] = 0;
        __syncthreads();
        int b = threadIdx.x;
        if (b < NB) {
            if (which == 0) {
                float lo = g_selval[b*4+0]*(1.0f-FRLO) + g_selval[b*4+1]*FRLO;
                float hi = g_selval[b*4+2]*(1.0f-FRHI) + g_selval[b*4+3]*FRHI;
                g_lo[b] = lo;
                g_ihl[b] = 1.0f / (hi - lo + EPS_C);
            } else {
                float med = 0.5f * (g_selval[b*2+0] + g_selval[b*2+1]);
                g_isig[b] = 1.0f / fmaxf(med, EPS_C);
            }
        }
    }
}

// ---------------- N_hat + grad magnitude ----------------
__global__ void k_nhat() {
    int b = blockIdx.z;
    int j = blockIdx.x * 32 + threadIdx.x;
    int i = blockIdx.y * 8 + threadIdx.y;
    size_t base = (size_t)b*NPIX;
    float lo = g_lo[b], inv = g_ihl[b];
    size_t o = base + (size_t)i*512 + j;
    float xc = __ldg(&g_x[o]);
    float n00 = fminf(fmaxf((xc - lo) * inv, 0.0f), 1.0f);
    float dx = 0.0f, dy = 0.0f;
    if (j < 511) {
        float xr = __ldg(&g_x[o + 1]);
        dx = fminf(fmaxf((xr - lo) * inv, 0.0f), 1.0f) - n00;
    }
    if (i < 511) {
        float xd = __ldg(&g_x[o + 512]);
        dy = fminf(fmaxf((xd - lo) * inv, 0.0f), 1.0f) - n00;
    }
    g_Nh[o] = n00;
    g_gm[o] = sqrtf(dx*dx + dy*dy + EPS_C);
}

// ---------------- bounds alpha*Wx, alpha*Wy (fast exp) ----------------
__global__ void k_wxy() {
    int b = blockIdx.z;
    int j = blockIdx.x * 32 + threadIdx.x;
    int i = blockIdx.y * 8 + threadIdx.y;
    size_t base = (size_t)b*NPIX;
    float isig = g_isig[b];
    size_t o = base + (size_t)i*512 + j;
    float n00 = __ldg(&g_Nh[o]);
    float dx = (j < 511) ? (__ldg(&g_Nh[o + 1]) - n00) : 0.0f;
    float dy = (i < 511) ? (__ldg(&g_Nh[o + 512]) - n00) : 0.0f;
    g_Wx[o] = ALPHA_C * (1.0f + MU_C * __expf(-fabsf(dx) * isig));
    g_Wy[o] = ALPHA_C * (1.0f + MU_C * __expf(-fabsf(dy) * isig));
}

// ---------------- fused primal-dual: KK iterations per launch ----------------
// Registers hold u, Nh, bx(=aWx), by(=aWy); px/py/ub live in smem.
// Thread layout (60, 8): column fixed per thread; valid rect shrinks per iter,
// pinned at true image edges; after KK iters the TTxTT interior is exact.
template<bool FIRST, bool LAST>
__global__ void __launch_bounds__(NTH, 2) k_pdfuse(int rd, int wr, float* __restrict__ out) {
    extern __shared__ float sm[];
    float* s_ub = sm;
    float* s_px = sm + SMSZ;
    float* s_py = sm + 2*SMSZ;

    int b = blockIdx.z;
    int rx0 = blockIdx.x * TT - KK;
    int ry0 = blockIdx.y * TT - KK;
    size_t base = (size_t)b * NPIX;
    int tx = threadIdx.x;            // local column 0..59
    int ty = threadIdx.y;            // row group 0..7
    int gj = rx0 + tx;
    bool jok = (gj >= 0) && (gj < 512);

    float ru[PPT], rnh[PPT], rbx[PPT], rby[PPT];

    // ---- load ----
    #pragma unroll
    for (int k = 0; k < PPT; k++) {
        int r = ty + 8*k;
        if (r < SS) {
            int gi = ry0 + r;
            int o = r*PITCH + tx;
            if (jok && gi >= 0 && gi < 512) {
                size_t go = base + (size_t)gi*512 + gj;
                float nh = __ldg(&g_Nh[go]);
                rnh[k] = nh;
                rbx[k] = __ldg(&g_Wx[go]);
                rby[k] = __ldg(&g_Wy[go]);
                if (FIRST) {
                    ru[k] = nh; s_ub[o] = nh;
                    s_px[o] = 0.0f; s_py[o] = 0.0f;
                } else {
                    ru[k]  = __ldg(&g_u [rd][go]);
                    s_ub[o] = __ldg(&g_ub[rd][go]);
                    s_px[o] = __ldg(&g_px[rd][go]);
                    s_py[o] = __ldg(&g_py[rd][go]);
                }
            }
        }
    }
    __syncthreads();

    // valid rectangle (local coords); pinned at true image edges
    int rA = (ry0 < 0) ? -ry0 : 0;
    int rB = (511 - ry0 < SS-1) ? (511 - ry0) : (SS-1);
    int cA = (rx0 < 0) ? -rx0 : 0;
    int cB = (511 - rx0 < SS-1) ? (511 - rx0) : (SS-1);

    for (int t = 0; t < KK; t++) {
        // ---- dual phase over [rA,rB]x[cA,cB] ----
        bool cok = (tx >= cA) && (tx <= cB);
        #pragma unroll
        for (int k = 0; k < PPT; k++) {
            int r = ty + 8*k;
            if (r < SS && cok && r >= rA && r <= rB) {
                int gi = ry0 + r;
                int o = r*PITCH + tx;
                float ubc = s_ub[o];
                float dx = (gj < 511) ? (s_ub[o + 1]     - ubc) : 0.0f;
                float dy = (gi < 511) ? (s_ub[o + PITCH] - ubc) : 0.0f;
                float pxn = fminf(fmaxf(s_px[o] + SIG*dx, -rbx[k]), rbx[k]);
                float pyn = fminf(fmaxf(s_py[o] + SIG*dy, -rby[k]), rby[k]);
                s_px[o] = pxn; s_py[o] = pyn;
            }
        }
        __syncthreads();

        int rA2 = rA + ((ry0 + rA) != 0);
        int rB2 = rB - ((ry0 + rB) != 511);
        int cA2 = cA + ((rx0 + cA) != 0);
        int cB2 = cB - ((rx0 + cB) != 511);

        // ---- primal phase over shrunk rect ----
        bool cok2 = (tx >= cA2) && (tx <= cB2);
        #pragma unroll
        for (int k = 0; k < PPT; k++) {
            int r = ty + 8*k;
            if (r < SS && cok2 && r >= rA2 && r <= rB2) {
                int gi = ry0 + r;
                int o = r*PITCH + tx;
                float pxl = (gj > 0) ? s_px[o - 1]     : 0.0f;
                float pyu = (gi > 0) ? s_py[o - PITCH] : 0.0f;
                float uc = ru[k];
                float un = (uc + TAUC*(s_px[o] - pxl + s_py[o] - pyu) + TAUC*rnh[k]) * INV1T;
                s_ub[o] = 2.0f*un - uc;
                ru[k] = un;
            }
        }
        __syncthreads();
        rA = rA2; rB = rB2; cA = cA2; cB = cB2;
    }

    // ---- store interior [KK, KK+TT) (guard against tile overhang) ----
    if (tx >= KK && tx < KK+TT && gj < 512) {
        #pragma unroll
        for (int k = 0; k < PPT; k++) {
            int r = ty + 8*k;
            if (r >= KK && r < KK+TT) {
                int gi = ry0 + r;
                if (gi < 512) {
                    size_t go = base + (size_t)gi*512 + gj;
                    int o = r*PITCH + tx;
                    if (LAST) {
                        out[go] = fminf(fmaxf(ru[k], 0.0f), 1.0f);
                    } else {
                        g_u [wr][go] = ru[k];
                        g_ub[wr][go] = s_ub[o];
                        g_px[wr][go] = s_px[o];
                        g_py[wr][go] = s_py[o];
                    }
                }
            }
        }
    }
}

// ---------------- launch ----------------
extern "C" void kernel_launch(void* const* d_in, const int* in_sizes, int n_in,
                              void* d_out, int out_size) {
    const float* Iy = (const float*)d_in[0];
    float* out = (float*)d_out;

    const int smbytes = 3 * SMSZ * sizeof(float);
    cudaFuncSetAttribute(k_pdfuse<true,false>,  cudaFuncAttributeMaxDynamicSharedMemorySize, smbytes);
    cudaFuncSetAttribute(k_pdfuse<false,false>, cudaFuncAttributeMaxDynamicSharedMemorySize, smbytes);
    cudaFuncSetAttribute(k_pdfuse<false,true>,  cudaFuncAttributeMaxDynamicSharedMemorySize, smbytes);

    dim3 b32x8(32, 8);
    dim3 gFull(16, 64, NB);

    k_hpool  <<<dim3(512, NB), 512>>>(Iy);
    k_vpool_x<<<dim3(16, 8, NB), b32x8>>>(Iy);

    k_zero_hists<<<16, 256>>>();

    // quantiles of x (p01, p99): ranks k and k+1 for linear interpolation
    k_hist1<<<dim3(64, NB), 256>>>(0);
    k_resolve<<<1, 256>>>(64, 4, 1, 0);
    for (int pass = 2; pass <= 4; pass++) {
        k_histT<<<dim3(32, 64), 256>>>(0, 4, pass);
        k_resolve<<<1, 256>>>(64, 4, pass, 0);
    }

    k_nhat<<<gFull, b32x8>>>();

    // median of grad magnitude
    k_hist1<<<dim3(64, NB), 256>>>(1);
    k_resolve<<<1, 256>>>(32, 2, 1, 1);
    for (int pass = 2; pass <= 4; pass++) {
        k_histT<<<dim3(32, 32), 256>>>(1, 2, pass);
        k_resolve<<<1, 256>>>(32, 2, pass, 1);
    }

    k_wxy<<<gFull, b32x8>>>();

    // 30 PD iterations = 5 fused launches of 6
    dim3 bTile(SS, 8);
    dim3 gTile(NTILE, NTILE, NB);
    k_pdfuse<true,  false><<<gTile, bTile, smbytes>>>(0, 0, nullptr);
    k_pdfuse<false, false><<<gTile, bTile, smbytes>>>(0, 1, nullptr);
    k_pdfuse<false, false><<<gTile, bTile, smbytes>>>(1, 0, nullptr);
    k_pdfuse<false, false><<<gTile, bTile, smbytes>>>(0, 1, nullptr);
    k_pdfuse<false, true ><<<gTile, bTile, smbytes>>>(1, 0, out);
}